// round 1
// baseline (speedup 1.0000x reference)
#include <cuda_runtime.h>
#include <math.h>

// Problem constants
#define NB 2
#define NV 5023
#define NF 2048
#define IH 256
#define IW 256
#define PP (IH * IW)

// Per-face precomputed data, SoA: [component][b*NF + f]
// 0:A0=y1-y2  1:B0=x2-x1  2:A1=y2-y0  3:B1=x0-x2  4:x2  5:y2  6:inv
// 7:z0 8:z1 9:z2  10:xmin 11:xmax 12:ymin 13:ymax
__device__ float g_face[14][NB * NF];
// Per-vertex sampled texture color: [b*NV + v]*3 + c
__device__ float g_vcol[NB * NV * 3];

__global__ void face_pre(const float* __restrict__ tv, const int* __restrict__ faces) {
    int idx = blockIdx.x * blockDim.x + threadIdx.x;
    if (idx >= NB * NF) return;
    int b = idx / NF, f = idx % NF;
    int i0 = faces[f * 3 + 0];
    int i1 = faces[f * 3 + 1];
    int i2 = faces[f * 3 + 2];
    const float* p0 = tv + ((size_t)b * NV + i0) * 3;
    const float* p1 = tv + ((size_t)b * NV + i1) * 3;
    const float* p2 = tv + ((size_t)b * NV + i2) * 3;
    float x0 = p0[0], y0 = p0[1], z0 = p0[2];
    float x1 = p1[0], y1 = p1[1], z1 = p1[2];
    float x2 = p2[0], y2 = p2[1], z2 = p2[2];

    float denom = (y1 - y2) * (x0 - x2) + (x2 - x1) * (y0 - y2);
    bool valid = fabsf(denom) > 1e-8f;
    float inv = valid ? (1.0f / denom) : 0.0f;

    g_face[0][idx] = y1 - y2;
    g_face[1][idx] = x2 - x1;
    g_face[2][idx] = y2 - y0;
    g_face[3][idx] = x0 - x2;
    g_face[4][idx] = x2;
    g_face[5][idx] = y2;
    g_face[6][idx] = inv;
    g_face[7][idx] = z0;
    g_face[8][idx] = z1;
    g_face[9][idx] = z2;

    float xmn = fminf(x0, fminf(x1, x2));
    float xmx = fmaxf(x0, fmaxf(x1, x2));
    float ymn = fminf(y0, fminf(y1, y2));
    float ymx = fmaxf(y0, fmaxf(y1, y2));
    if (!valid) { xmn = 2e30f; xmx = -2e30f; ymn = 2e30f; ymx = -2e30f; }
    g_face[10][idx] = xmn;
    g_face[11][idx] = xmx;
    g_face[12][idx] = ymn;
    g_face[13][idx] = ymx;
}

__global__ void vcol_pre(const float* __restrict__ tex, const float* __restrict__ uv) {
    int idx = blockIdx.x * blockDim.x + threadIdx.x;
    if (idx >= NB * NV) return;
    int b = idx / NV, v = idx % NV;
    float u = uv[v * 2 + 0] * 255.0f;   // (Wt-1)
    float vv = uv[v * 2 + 1] * 255.0f;  // (Ht-1)
    float u0f = floorf(u);
    float v0f = floorf(vv);
    u0f = fminf(fmaxf(u0f, 0.0f), 254.0f);
    v0f = fminf(fmaxf(v0f, 0.0f), 254.0f);
    int u0 = (int)u0f;
    int v0 = (int)v0f;
    float fu = u - u0f;
    float fv = vv - v0f;
    const float* t = tex + (size_t)b * 256 * 256 * 3;
    const float* r0 = t + ((size_t)v0 * 256 + u0) * 3;
    const float* r1 = t + ((size_t)(v0 + 1) * 256 + u0) * 3;
#pragma unroll
    for (int c = 0; c < 3; c++) {
        float c00 = r0[c];
        float c01 = r0[3 + c];
        float c10 = r1[c];
        float c11 = r1[3 + c];
        float top = c00 * (1.0f - fu) + c01 * fu;
        float bot = c10 * (1.0f - fu) + c11 * fu;
        g_vcol[idx * 3 + c] = top * (1.0f - fv) + bot * fv;
    }
}

#define TF 256  // faces per smem tile

__global__ void raster(const float* __restrict__ verts,
                       const int* __restrict__ faces,
                       float* __restrict__ out) {
    __shared__ float sA0[TF], sB0[TF], sA1[TF], sB1[TF];
    __shared__ float sx2[TF], sy2[TF], sinv[TF];
    __shared__ float sz0[TF], sz1[TF], sz2[TF];
    __shared__ int sfid[TF];
    __shared__ int scount;

    const int b = blockIdx.z;
    const int tx = threadIdx.x, ty = threadIdx.y;
    const int tid = ty * 16 + tx;
    const int px_i = blockIdx.x * 16 + tx;
    const int py_i = blockIdx.y * 16 + ty;

    const float px = (px_i + 0.5f) / 256.0f * 2.0f - 1.0f;
    const float py = (py_i + 0.5f) / 256.0f * 2.0f - 1.0f;

    // conservative tile bounds in NDC (expanded a hair for float-boundary safety)
    const float eps = 1e-4f;
    const float blk_xmin = (blockIdx.x * 16 + 0.5f)  / 256.0f * 2.0f - 1.0f - eps;
    const float blk_xmax = (blockIdx.x * 16 + 15.5f) / 256.0f * 2.0f - 1.0f + eps;
    const float blk_ymin = (blockIdx.y * 16 + 0.5f)  / 256.0f * 2.0f - 1.0f - eps;
    const float blk_ymax = (blockIdx.y * 16 + 15.5f) / 256.0f * 2.0f - 1.0f + eps;

    float bz = -1.0f;
    int bf = -1;
    float bw0 = 0.0f, bw1 = 0.0f, bw2 = 0.0f;

    for (int base = 0; base < NF; base += TF) {
        if (tid == 0) scount = 0;
        __syncthreads();

        // compact faces overlapping this tile (order-free; tie-break fixes order)
        {
            int f = base + tid;
            int gi = b * NF + f;
            float xmn = g_face[10][gi];
            float xmx = g_face[11][gi];
            float ymn = g_face[12][gi];
            float ymx = g_face[13][gi];
            if (xmx >= blk_xmin && xmn <= blk_xmax && ymx >= blk_ymin && ymn <= blk_ymax) {
                int slot = atomicAdd(&scount, 1);
                sA0[slot] = g_face[0][gi];
                sB0[slot] = g_face[1][gi];
                sA1[slot] = g_face[2][gi];
                sB1[slot] = g_face[3][gi];
                sx2[slot] = g_face[4][gi];
                sy2[slot] = g_face[5][gi];
                sinv[slot] = g_face[6][gi];
                sz0[slot] = g_face[7][gi];
                sz1[slot] = g_face[8][gi];
                sz2[slot] = g_face[9][gi];
                sfid[slot] = f;
            }
        }
        __syncthreads();

        const int cnt = scount;
        for (int j = 0; j < cnt; j++) {
            float dx = px - sx2[j];
            float dy = py - sy2[j];
            float inv = sinv[j];
            float w0 = (sA0[j] * dx + sB0[j] * dy) * inv;
            float w1 = (sA1[j] * dx + sB1[j] * dy) * inv;
            float w2 = 1.0f - w0 - w1;
            if (w0 >= 0.0f && w1 >= 0.0f && w2 >= 0.0f) {
                float z = w0 * sz0[j] + w1 * sz1[j] + w2 * sz2[j];
                int f2 = sfid[j];
                // sequential semantics: strict-> update; among exact z ties the
                // smallest face index wins (first occurrence in scan/argmax).
                if (z > bz || (z == bz && bf >= 0 && f2 < bf)) {
                    bz = z; bf = f2;
                    bw0 = w0; bw1 = w1; bw2 = w2;
                }
            }
        }
        __syncthreads();
    }

    // ---- shading ----
    const int p = py_i * IW + px_i;
    const float alpha = (bf >= 0) ? 1.0f : 0.0f;
    const int sf = (bf >= 0) ? bf : 0;
    const int i0 = faces[sf * 3 + 0];
    const int i1 = faces[sf * 3 + 1];
    const int i2 = faces[sf * 3 + 2];

    const float* c0 = &g_vcol[((size_t)b * NV + i0) * 3];
    const float* c1 = &g_vcol[((size_t)b * NV + i1) * 3];
    const float* c2 = &g_vcol[((size_t)b * NV + i2) * 3];
    const float* v0 = verts + ((size_t)b * NV + i0) * 3;
    const float* v1 = verts + ((size_t)b * NV + i1) * 3;
    const float* v2 = verts + ((size_t)b * NV + i2) * 3;

    float ch[6];
#pragma unroll
    for (int c = 0; c < 3; c++)
        ch[c] = c0[c] * bw0 + c1[c] * bw1 + c2[c] * bw2;
#pragma unroll
    for (int c = 0; c < 3; c++)
        ch[3 + c] = v0[c] * bw0 + v1[c] * bw1 + v2[c] * bw2;

    // output layout: rendered (B,6,H,W) | alpha (B,1,H,W) | fid (B,H,W) | zbuf (B,H,W)
    float* rend = out;
    float* al   = out + (size_t)NB * 6 * PP;
    float* fo   = al  + (size_t)NB * PP;
    float* zo   = fo  + (size_t)NB * PP;

#pragma unroll
    for (int c = 0; c < 6; c++)
        rend[((size_t)b * 6 + c) * PP + p] = ch[c] * alpha;
    al[(size_t)b * PP + p] = alpha;
    fo[(size_t)b * PP + p] = (float)bf;
    zo[(size_t)b * PP + p] = bz;
}

extern "C" void kernel_launch(void* const* d_in, const int* in_sizes, int n_in,
                              void* d_out, int out_size) {
    const float* vertices = (const float*)d_in[0];
    const float* tverts   = (const float*)d_in[1];
    const float* tex      = (const float*)d_in[2];
    const float* uv       = (const float*)d_in[3];
    const int*   faces    = (const int*)d_in[4];
    float* out = (float*)d_out;

    face_pre<<<(NB * NF + 255) / 256, 256>>>(tverts, faces);
    vcol_pre<<<(NB * NV + 255) / 256, 256>>>(tex, uv);
    dim3 grid(IW / 16, IH / 16, NB);
    dim3 blk(16, 16);
    raster<<<grid, blk>>>(vertices, faces, out);
}